// round 14
// baseline (speedup 1.0000x reference)
#include <cuda_runtime.h>
#include <cuda_bf16.h>

#define NN 50000
#define NE 800000
#define NIDX 25000

typedef unsigned long long ull;

#define EB 2500            // edge-kernel blocks: 640000 threads
#define NSL8 40000         // half-warp slots (edge8): NE/NSL8 = 20 edges/slot exact
#define NW16 20000         // warps (edge16):         NE/NW16 = 40 edges/warp exact
#define IT8  20            // edges per slot (edge8)
#define IT16 40            // edges per warp (edge16)

// Scratch (__device__ globals; zero-initialized at module load).
// Invariants at START of every kernel_launch call:
//   g_deg == 0 (re-zeroed by last node kernel), g_aggr == 0 (re-zeroed by every node kernel).
__device__ float  g_deg [NN];
__device__ float  g_aggr[NN * 16];
__device__ float  g_h1  [NN * 16];
__device__ float  g_h2  [NN * 16];
__device__ float4 g_pseudo[NE];
__device__ ull    g_sd  [NE];      // (dst<<32)|src per edge, built by edge8

// ---- packed f32x2 helpers -------------------------------------------------
__device__ __forceinline__ ull ffma2(ull a, ull b, ull c) {
    ull d;
    asm("fma.rn.f32x2 %0, %1, %2, %3;" : "=l"(d) : "l"(a), "l"(b), "l"(c));
    return d;
}
__device__ __forceinline__ ull pack2(float lo, float hi) {
    ull r;
    asm("mov.b64 %0, {%1, %2};" : "=l"(r) : "f"(lo), "f"(hi));
    return r;
}
__device__ __forceinline__ void unpack2(ull v, float& lo, float& hi) {
    asm("mov.b64 {%0, %1}, %2;" : "=f"(lo), "=f"(hi) : "l"(v));
}
__device__ __forceinline__ ull relu2(ull v) {
    float lo, hi;
    unpack2(v, lo, hi);
    lo = fmaxf(lo, 0.0f);
    hi = fmaxf(hi, 0.0f);
    return pack2(lo, hi);
}
__device__ __forceinline__ void red_v4(float* p, float a, float b, float c, float d) {
    asm volatile("red.global.add.v4.f32 [%0], {%1, %2, %3, %4};"
                 :: "l"(p), "f"(a), "f"(b), "f"(c), "f"(d) : "memory");
}

// Collect co-quads and issue one red.v4 per 4 lanes. ALL 32 lanes must reach this.
__device__ __forceinline__ void quad_red(float sum, int co, bool active, float* addr) {
    float b  = __shfl_xor_sync(0xffffffffu, sum, 1);
    float v0 = (co & 1) ? b : sum;
    float v1 = (co & 1) ? sum : b;
    float c0 = __shfl_xor_sync(0xffffffffu, v0, 2);
    float c1 = __shfl_xor_sync(0xffffffffu, v1, 2);
    if (active && (co & 3) == 0) red_v4(addr, v0, v1, c0, c1);
}

// Fold edge-MLP params into smem (packed over ci-pairs).
// As floats: sf[((k*4+c)*16+co)*2 + (ci&1)], k = ci>>1, c in {Wx,Wy,Wz,const}.
__device__ __forceinline__ void fold_smem(float* sf,
                                          const float* __restrict__ lw,
                                          const float* __restrict__ lb,
                                          const float* __restrict__ ga,
                                          const float* __restrict__ be, int D)
{
    for (int j = threadIdx.x; j < D; j += blockDim.x) {
        float g = ga[j];
        float c0 = lw[j] * g;
        float c1 = lw[D + j] * g;
        float c2 = lw[2 * D + j] * g;
        float c3 = fmaf(lb[j], g, be[j]);
        int ci = j >> 4, co = j & 15;
        int k = ci >> 1, h = ci & 1;
        sf[((k * 4 + 0) * 16 + co) * 2 + h] = c0;
        sf[((k * 4 + 1) * 16 + co) * 2 + h] = c1;
        sf[((k * 4 + 2) * 16 + co) * 2 + h] = c2;
        sf[((k * 4 + 3) * 16 + co) * 2 + h] = c3;
    }
    __syncthreads();
}

// ---------------------------------------------------------------------------
// Layer-0 edge kernel (CI=8): half-warp per edge (lane = co).
// Software-pipelined pairs; also emits pseudo + packed sd + degree.
__global__ void __launch_bounds__(256)
edge8_kernel(const float* __restrict__ x,     // [NN, 8]
             const float* __restrict__ pos,   // [NN, 3]
             const int*   __restrict__ ei,    // [2, NE]
             const float* __restrict__ lw, const float* __restrict__ lb,
             const float* __restrict__ ga, const float* __restrict__ be,
             float* __restrict__ aggr)        // [NN, 16]
{
    __shared__ ull sP[4 * 4 * 16];
    fold_smem((float*)sP, lw, lb, ga, be, 128);

    int co = threadIdx.x & 15;
    ull Px[4], Py[4], Pz[4], Pc[4];
#pragma unroll
    for (int k = 0; k < 4; k++) {
        Px[k] = sP[(k * 4 + 0) * 16 + co];
        Py[k] = sP[(k * 4 + 1) * 16 + co];
        Pz[k] = sP[(k * 4 + 2) * 16 + co];
        Pc[k] = sP[(k * 4 + 3) * 16 + co];
    }

    int slot = (blockIdx.x * 256 + threadIdx.x) >> 4;   // 0..NSL8-1

    // prefetch first pair's indices
    int eA = slot, eB = slot + NSL8;
    int sA = __ldg(&ei[eA]), dA = __ldg(&ei[NE + eA]);
    int sB = __ldg(&ei[eB]), dB = __ldg(&ei[NE + eB]);

    for (int k = 0; k < IT8; k += 2) {
        // dependent loads for current pair (issued first)
        float ax = __ldg(&pos[dA * 3 + 0]) - __ldg(&pos[sA * 3 + 0]);
        float ay = __ldg(&pos[dA * 3 + 1]) - __ldg(&pos[sA * 3 + 1]);
        float az = __ldg(&pos[dA * 3 + 2]) - __ldg(&pos[sA * 3 + 2]);
        float bx = __ldg(&pos[dB * 3 + 0]) - __ldg(&pos[sB * 3 + 0]);
        float by = __ldg(&pos[dB * 3 + 1]) - __ldg(&pos[sB * 3 + 1]);
        float bz = __ldg(&pos[dB * 3 + 2]) - __ldg(&pos[sB * 3 + 2]);
        const ulonglong2* xrA = (const ulonglong2*)(x + (size_t)sA * 8);
        const ulonglong2* xrB = (const ulonglong2*)(x + (size_t)sB * 8);
        ulonglong2 vA0 = __ldg(&xrA[0]), vA1 = __ldg(&xrA[1]);
        ulonglong2 vB0 = __ldg(&xrB[0]), vB1 = __ldg(&xrB[1]);

        int cdA = dA, cdB = dB, csA = sA, csB = sB;
        int ceA = eA, ceB = eB;

        // prefetch next pair's indices (independent of compute below)
        if (k + 2 < IT8) {
            eA += 2 * NSL8; eB += 2 * NSL8;
            sA = __ldg(&ei[eA]); dA = __ldg(&ei[NE + eA]);
            sB = __ldg(&ei[eB]); dB = __ldg(&ei[NE + eB]);
        }

        if (co == 0) {
            g_pseudo[ceA] = make_float4(ax, ay, az, 0.f);
            g_pseudo[ceB] = make_float4(bx, by, bz, 0.f);
            atomicAdd(&g_deg[cdA], 1.0f);
            atomicAdd(&g_deg[cdB], 1.0f);
        } else if (co == 1) {
            g_sd[ceA] = ((ull)(unsigned)cdA << 32) | (unsigned)csA;
            g_sd[ceB] = ((ull)(unsigned)cdB << 32) | (unsigned)csB;
        }

        // edge A
        {
            ull p0 = pack2(ax, ax), p1 = pack2(ay, ay), p2 = pack2(az, az);
            ull xv[4] = { vA0.x, vA0.y, vA1.x, vA1.y };
            ull acc = 0;
#pragma unroll
            for (int q = 0; q < 4; q++) {
                ull w = ffma2(p2, Pz[q], Pc[q]);
                w = ffma2(p1, Py[q], w);
                w = ffma2(p0, Px[q], w);
                w = relu2(w);
                acc = ffma2(xv[q], w, acc);
            }
            float lo, hi; unpack2(acc, lo, hi);
            quad_red(lo + hi, co, true, &aggr[(size_t)cdA * 16 + co]);
        }
        // edge B
        {
            ull p0 = pack2(bx, bx), p1 = pack2(by, by), p2 = pack2(bz, bz);
            ull xv[4] = { vB0.x, vB0.y, vB1.x, vB1.y };
            ull acc = 0;
#pragma unroll
            for (int q = 0; q < 4; q++) {
                ull w = ffma2(p2, Pz[q], Pc[q]);
                w = ffma2(p1, Py[q], w);
                w = ffma2(p0, Px[q], w);
                w = relu2(w);
                acc = ffma2(xv[q], w, acc);
            }
            float lo, hi; unpack2(acc, lo, hi);
            quad_red(lo + hi, co, true, &aggr[(size_t)cdB * 16 + co]);
        }
    }
}

// ---------------------------------------------------------------------------
// CI=16 edge kernel: FULL warp per edge. ci split across half-warps
// (half h handles ci in [8h, 8h+8)), combined via shfl_xor(16). Pipelined pairs.
// Indices come from the packed g_sd word: ONE LDG.64 per edge instead of two
// strided LDG.32s.
__global__ void __launch_bounds__(256)
edge16_kernel(const float* __restrict__ hin,  // [NN, 16]
              const float* __restrict__ lw, const float* __restrict__ lb,
              const float* __restrict__ ga, const float* __restrict__ be,
              float* __restrict__ aggr)       // [NN, 16]
{
    __shared__ ull sP[8 * 4 * 16];
    fold_smem((float*)sP, lw, lb, ga, be, 256);

    int lane = threadIdx.x & 31;
    int co   = lane & 15;
    int half = lane >> 4;

    ull Px[4], Py[4], Pz[4], Pc[4];
#pragma unroll
    for (int k = 0; k < 4; k++) {
        int kg = half * 4 + k;
        Px[k] = sP[(kg * 4 + 0) * 16 + co];
        Py[k] = sP[(kg * 4 + 1) * 16 + co];
        Pz[k] = sP[(kg * 4 + 2) * 16 + co];
        Pc[k] = sP[(kg * 4 + 3) * 16 + co];
    }

    int w = (blockIdx.x * 256 + threadIdx.x) >> 5;   // 0..NW16-1

    int eA = w, eB = w + NW16;
    ull sdA = __ldg(&g_sd[eA]);
    ull sdB = __ldg(&g_sd[eB]);
    float4 psA = __ldg(&g_pseudo[eA]);
    float4 psB = __ldg(&g_pseudo[eB]);

    for (int k = 0; k < IT16; k += 2) {
        int sA = (int)(unsigned)(sdA & 0xffffffffu);
        int cdA = (int)(unsigned)(sdA >> 32);
        int sB = (int)(unsigned)(sdB & 0xffffffffu);
        int cdB = (int)(unsigned)(sdB >> 32);

        // x gathers for current pair (only dependent loads in flight)
        const ulonglong2* xrA = (const ulonglong2*)(hin + (size_t)sA * 16) + half * 2;
        const ulonglong2* xrB = (const ulonglong2*)(hin + (size_t)sB * 16) + half * 2;
        ulonglong2 vA0 = __ldg(&xrA[0]), vA1 = __ldg(&xrA[1]);
        ulonglong2 vB0 = __ldg(&xrB[0]), vB1 = __ldg(&xrB[1]);

        float4 cpA = psA, cpB = psB;

        // prefetch next pair
        if (k + 2 < IT16) {
            eA += 2 * NW16; eB += 2 * NW16;
            sdA = __ldg(&g_sd[eA]);
            sdB = __ldg(&g_sd[eB]);
            psA = __ldg(&g_pseudo[eA]);
            psB = __ldg(&g_pseudo[eB]);
        }

        // edge A
        {
            ull p0 = pack2(cpA.x, cpA.x), p1 = pack2(cpA.y, cpA.y), p2 = pack2(cpA.z, cpA.z);
            ull xv[4] = { vA0.x, vA0.y, vA1.x, vA1.y };
            ull acc = 0;
#pragma unroll
            for (int q = 0; q < 4; q++) {
                ull t = ffma2(p2, Pz[q], Pc[q]);
                t = ffma2(p1, Py[q], t);
                t = ffma2(p0, Px[q], t);
                t = relu2(t);
                acc = ffma2(xv[q], t, acc);
            }
            float lo, hi; unpack2(acc, lo, hi);
            float sum = lo + hi;
            sum += __shfl_xor_sync(0xffffffffu, sum, 16);
            quad_red(sum, co, lane < 16, &aggr[(size_t)cdA * 16 + co]);
        }
        // edge B
        {
            ull p0 = pack2(cpB.x, cpB.x), p1 = pack2(cpB.y, cpB.y), p2 = pack2(cpB.z, cpB.z);
            ull xv[4] = { vB0.x, vB0.y, vB1.x, vB1.y };
            ull acc = 0;
#pragma unroll
            for (int q = 0; q < 4; q++) {
                ull t = ffma2(p2, Pz[q], Pc[q]);
                t = ffma2(p1, Py[q], t);
                t = ffma2(p0, Px[q], t);
                t = relu2(t);
                acc = ffma2(xv[q], t, acc);
            }
            float lo, hi; unpack2(acc, lo, hi);
            float sum = lo + hi;
            sum += __shfl_xor_sync(0xffffffffu, sum, 16);
            quad_red(sum, co, lane < 16, &aggr[(size_t)cdB * 16 + co]);
        }
    }
}

// ---------------------------------------------------------------------------
// Node kernel: 4 threads per node (thread = co-quad). Re-zeroes aggr (+deg on last).
template<int CI, bool ZERODEG>
__global__ void __launch_bounds__(256)
node_kernel(const float* __restrict__ hin,
            const float* __restrict__ root,  // [CI, 16]
            const float* __restrict__ bias,  // [16]
            float* __restrict__ aggr,
            float* __restrict__ hout)        // [NN, 16]
{
    int i = blockIdx.x * blockDim.x + threadIdx.x;
    int n = i >> 2, q = i & 3;
    if (n >= NN) return;

    float inv = 1.0f / fmaxf(g_deg[n], 1.0f);
    if (ZERODEG && q == 0) g_deg[n] = 0.0f;

    float4* ar = (float4*)(aggr + (size_t)n * 16) + q;
    float4 a = *ar;
    float4 bi = __ldg((const float4*)bias + q);
    float acc0 = fmaf(a.x, inv, bi.x);
    float acc1 = fmaf(a.y, inv, bi.y);
    float acc2 = fmaf(a.z, inv, bi.z);
    float acc3 = fmaf(a.w, inv, bi.w);

#pragma unroll
    for (int ci = 0; ci < CI; ci++) {
        float xv = __ldg(&hin[(size_t)n * CI + ci]);
        float4 r = __ldg((const float4*)(root + ci * 16) + q);
        acc0 = fmaf(xv, r.x, acc0);
        acc1 = fmaf(xv, r.y, acc1);
        acc2 = fmaf(xv, r.z, acc2);
        acc3 = fmaf(xv, r.w, acc3);
    }

    float4 o;
    o.x = fmaxf(acc0, 0.0f);
    o.y = fmaxf(acc1, 0.0f);
    o.z = fmaxf(acc2, 0.0f);
    o.w = fmaxf(acc3, 0.0f);
    ((float4*)(hout + (size_t)n * 16))[q] = o;
    *ar = make_float4(0.f, 0.f, 0.f, 0.f);   // reset aggr for next layer / call
}

// ---------------------------------------------------------------------------
__global__ void gather_kernel(const float* __restrict__ h,
                              const float* __restrict__ pos,
                              const int*   __restrict__ batch,
                              const int*   __restrict__ idx,
                              float* __restrict__ out)
{
    int i = blockIdx.x * blockDim.x + threadIdx.x;
    if (i >= NIDX) return;
    int n = idx[i];
    float4* od = (float4*)(out + (size_t)i * 16);
    const float4* hs = (const float4*)(h + (size_t)n * 16);
#pragma unroll
    for (int q = 0; q < 4; q++) od[q] = hs[q];
    out[NIDX * 16 + i * 3 + 0] = pos[n * 3 + 0];
    out[NIDX * 16 + i * 3 + 1] = pos[n * 3 + 1];
    out[NIDX * 16 + i * 3 + 2] = pos[n * 3 + 2];
    reinterpret_cast<int*>(out)[NIDX * 19 + i] = batch[n];
}

// ---------------------------------------------------------------------------
extern "C" void kernel_launch(void* const* d_in, const int* in_sizes, int n_in,
                              void* d_out, int out_size)
{
    const float* x   = (const float*)d_in[0];
    const float* pos = (const float*)d_in[1];
    const float* lw0 = (const float*)d_in[2],  *lb0 = (const float*)d_in[3],
               * g0  = (const float*)d_in[4],  *be0 = (const float*)d_in[5],
               * r0  = (const float*)d_in[6],  *bi0 = (const float*)d_in[7];
    const float* lw1 = (const float*)d_in[8],  *lb1 = (const float*)d_in[9],
               * g1  = (const float*)d_in[10], *be1 = (const float*)d_in[11],
               * r1  = (const float*)d_in[12], *bi1 = (const float*)d_in[13];
    const float* lw2 = (const float*)d_in[14], *lb2 = (const float*)d_in[15],
               * g2  = (const float*)d_in[16], *be2 = (const float*)d_in[17],
               * r2  = (const float*)d_in[18], *bi2 = (const float*)d_in[19];
    const int* batch = (const int*)d_in[20];
    const int* idx   = (const int*)d_in[21];
    const int* ei    = (const int*)d_in[22];
    float* out = (float*)d_out;

    float *aggr, *h1, *h2;
    cudaGetSymbolAddress((void**)&aggr, g_aggr);
    cudaGetSymbolAddress((void**)&h1,   g_h1);
    cudaGetSymbolAddress((void**)&h2,   g_h2);

    dim3 node_grid((NN * 4 + 255) / 256);

    // Layer 0 (CI=8): x -> h1. Also computes pseudo + packed sd + degree.
    edge8_kernel<<<EB, 256>>>(x, pos, ei, lw0, lb0, g0, be0, aggr);
    node_kernel<8, false><<<node_grid, 256>>>(x, r0, bi0, aggr, h1);

    // Layer 1 (CI=16): h1 -> h2
    edge16_kernel<<<EB, 256>>>(h1, lw1, lb1, g1, be1, aggr);
    node_kernel<16, false><<<node_grid, 256>>>(h1, r1, bi1, aggr, h2);

    // Layer 2 (CI=16): h2 -> h1
    edge16_kernel<<<EB, 256>>>(h2, lw2, lb2, g2, be2, aggr);
    node_kernel<16, true><<<node_grid, 256>>>(h2, r2, bi2, aggr, h1);

    gather_kernel<<<(NIDX + 255) / 256, 256>>>(h1, pos, batch, idx, out);
}

// round 15
// speedup vs baseline: 1.7612x; 1.7612x over previous
#include <cuda_runtime.h>
#include <cuda_bf16.h>

#define NN 50000
#define NE 800000
#define NIDX 25000

typedef unsigned long long ull;

#define EB 2500            // edge-kernel blocks: 640000 threads
#define NSL8 40000         // half-warp slots (edge8): NE/NSL8 = 20 edges/slot exact
#define NW16 20000         // warps (edge16):         NE/NW16 = 40 edges/warp exact
#define IT8  20            // edges per slot (edge8)
#define IT16 40            // edges per warp (edge16)

// Scratch (__device__ globals; zero-initialized at module load).
// Invariants at START of every kernel_launch call:
//   g_deg == 0 (re-zeroed by last node kernel), g_aggr == 0 (re-zeroed by every node kernel).
__device__ float  g_deg [NN];
__device__ float  g_aggr[NN * 16];
__device__ float  g_h1  [NN * 16];
__device__ float  g_h2  [NN * 16];
__device__ float4 g_pseudo[NE];

// ---- packed f32x2 helpers -------------------------------------------------
__device__ __forceinline__ ull ffma2(ull a, ull b, ull c) {
    ull d;
    asm("fma.rn.f32x2 %0, %1, %2, %3;" : "=l"(d) : "l"(a), "l"(b), "l"(c));
    return d;
}
__device__ __forceinline__ ull pack2(float lo, float hi) {
    ull r;
    asm("mov.b64 %0, {%1, %2};" : "=l"(r) : "f"(lo), "f"(hi));
    return r;
}
__device__ __forceinline__ void unpack2(ull v, float& lo, float& hi) {
    asm("mov.b64 {%0, %1}, %2;" : "=f"(lo), "=f"(hi) : "l"(v));
}
__device__ __forceinline__ ull relu2(ull v) {
    float lo, hi;
    unpack2(v, lo, hi);
    lo = fmaxf(lo, 0.0f);
    hi = fmaxf(hi, 0.0f);
    return pack2(lo, hi);
}
__device__ __forceinline__ void red_v4(float* p, float a, float b, float c, float d) {
    asm volatile("red.global.add.v4.f32 [%0], {%1, %2, %3, %4};"
                 :: "l"(p), "f"(a), "f"(b), "f"(c), "f"(d) : "memory");
}

// Collect co-quads and issue one red.v4 per 4 lanes. 'sum' = this lane's co value.
// Lanes with (co&3)==0 && active issue red.v4 covering co..co+3.
__device__ __forceinline__ void quad_red(float sum, int co, bool active, float* addr) {
    float b  = __shfl_xor_sync(0xffffffffu, sum, 1);
    float v0 = (co & 1) ? b : sum;
    float v1 = (co & 1) ? sum : b;
    float c0 = __shfl_xor_sync(0xffffffffu, v0, 2);
    float c1 = __shfl_xor_sync(0xffffffffu, v1, 2);
    if (active && (co & 3) == 0) red_v4(addr, v0, v1, c0, c1);
}

// Fold edge-MLP params into smem (packed over ci-pairs).
// As floats: sf[((k*4+c)*16+co)*2 + (ci&1)], k = ci>>1, c in {Wx,Wy,Wz,const}.
__device__ __forceinline__ void fold_smem(float* sf,
                                          const float* __restrict__ lw,
                                          const float* __restrict__ lb,
                                          const float* __restrict__ ga,
                                          const float* __restrict__ be, int D)
{
    for (int j = threadIdx.x; j < D; j += blockDim.x) {
        float g = ga[j];
        float c0 = lw[j] * g;
        float c1 = lw[D + j] * g;
        float c2 = lw[2 * D + j] * g;
        float c3 = fmaf(lb[j], g, be[j]);
        int ci = j >> 4, co = j & 15;
        int k = ci >> 1, h = ci & 1;
        sf[((k * 4 + 0) * 16 + co) * 2 + h] = c0;
        sf[((k * 4 + 1) * 16 + co) * 2 + h] = c1;
        sf[((k * 4 + 2) * 16 + co) * 2 + h] = c2;
        sf[((k * 4 + 3) * 16 + co) * 2 + h] = c3;
    }
    __syncthreads();
}

// ---------------------------------------------------------------------------
// Layer-0 edge kernel (CI=8): half-warp per edge (lane = co).
// Software-pipelined pairs; also computes pseudo (stored) and degree.
__global__ void __launch_bounds__(256)
edge8_kernel(const float* __restrict__ x,     // [NN, 8]
             const float* __restrict__ pos,   // [NN, 3]
             const int*   __restrict__ ei,    // [2, NE]
             const float* __restrict__ lw, const float* __restrict__ lb,
             const float* __restrict__ ga, const float* __restrict__ be,
             float* __restrict__ aggr)        // [NN, 16]
{
    __shared__ ull sP[4 * 4 * 16];
    fold_smem((float*)sP, lw, lb, ga, be, 128);

    int co = threadIdx.x & 15;
    ull Px[4], Py[4], Pz[4], Pc[4];
#pragma unroll
    for (int k = 0; k < 4; k++) {
        Px[k] = sP[(k * 4 + 0) * 16 + co];
        Py[k] = sP[(k * 4 + 1) * 16 + co];
        Pz[k] = sP[(k * 4 + 2) * 16 + co];
        Pc[k] = sP[(k * 4 + 3) * 16 + co];
    }

    int slot = (blockIdx.x * 256 + threadIdx.x) >> 4;   // 0..NSL8-1

    // prefetch first pair's indices
    int eA = slot, eB = slot + NSL8;
    int sA = __ldg(&ei[eA]), dA = __ldg(&ei[NE + eA]);
    int sB = __ldg(&ei[eB]), dB = __ldg(&ei[NE + eB]);

    for (int k = 0; k < IT8; k += 2) {
        // dependent loads for current pair (issued first)
        float ax = __ldg(&pos[dA * 3 + 0]) - __ldg(&pos[sA * 3 + 0]);
        float ay = __ldg(&pos[dA * 3 + 1]) - __ldg(&pos[sA * 3 + 1]);
        float az = __ldg(&pos[dA * 3 + 2]) - __ldg(&pos[sA * 3 + 2]);
        float bx = __ldg(&pos[dB * 3 + 0]) - __ldg(&pos[sB * 3 + 0]);
        float by = __ldg(&pos[dB * 3 + 1]) - __ldg(&pos[sB * 3 + 1]);
        float bz = __ldg(&pos[dB * 3 + 2]) - __ldg(&pos[sB * 3 + 2]);
        const ulonglong2* xrA = (const ulonglong2*)(x + (size_t)sA * 8);
        const ulonglong2* xrB = (const ulonglong2*)(x + (size_t)sB * 8);
        ulonglong2 vA0 = __ldg(&xrA[0]), vA1 = __ldg(&xrA[1]);
        ulonglong2 vB0 = __ldg(&xrB[0]), vB1 = __ldg(&xrB[1]);

        int cdA = dA, cdB = dB, ceA = eA, ceB = eB;

        // prefetch next pair's indices (independent of compute below)
        if (k + 2 < IT8) {
            eA += 2 * NSL8; eB += 2 * NSL8;
            sA = __ldg(&ei[eA]); dA = __ldg(&ei[NE + eA]);
            sB = __ldg(&ei[eB]); dB = __ldg(&ei[NE + eB]);
        }

        if (co == 0) {
            g_pseudo[ceA] = make_float4(ax, ay, az, 0.f);
            g_pseudo[ceB] = make_float4(bx, by, bz, 0.f);
            atomicAdd(&g_deg[cdA], 1.0f);
            atomicAdd(&g_deg[cdB], 1.0f);
        }

        // edge A
        {
            ull p0 = pack2(ax, ax), p1 = pack2(ay, ay), p2 = pack2(az, az);
            ull xv[4] = { vA0.x, vA0.y, vA1.x, vA1.y };
            ull acc = 0;
#pragma unroll
            for (int q = 0; q < 4; q++) {
                ull w = ffma2(p2, Pz[q], Pc[q]);
                w = ffma2(p1, Py[q], w);
                w = ffma2(p0, Px[q], w);
                w = relu2(w);
                acc = ffma2(xv[q], w, acc);
            }
            float lo, hi; unpack2(acc, lo, hi);
            quad_red(lo + hi, co, true, &aggr[(size_t)cdA * 16 + co]);
        }
        // edge B
        {
            ull p0 = pack2(bx, bx), p1 = pack2(by, by), p2 = pack2(bz, bz);
            ull xv[4] = { vB0.x, vB0.y, vB1.x, vB1.y };
            ull acc = 0;
#pragma unroll
            for (int q = 0; q < 4; q++) {
                ull w = ffma2(p2, Pz[q], Pc[q]);
                w = ffma2(p1, Py[q], w);
                w = ffma2(p0, Px[q], w);
                w = relu2(w);
                acc = ffma2(xv[q], w, acc);
            }
            float lo, hi; unpack2(acc, lo, hi);
            quad_red(lo + hi, co, true, &aggr[(size_t)cdB * 16 + co]);
        }
    }
}

// ---------------------------------------------------------------------------
// CI=16 edge kernel: FULL warp per edge. ci split across half-warps
// (half h handles ci in [8h, 8h+8)), combined via shfl_xor(16). Pipelined pairs.
__global__ void __launch_bounds__(256)
edge16_kernel(const float* __restrict__ hin,  // [NN, 16]
              const int*   __restrict__ ei,   // [2, NE]
              const float* __restrict__ lw, const float* __restrict__ lb,
              const float* __restrict__ ga, const float* __restrict__ be,
              float* __restrict__ aggr)       // [NN, 16]
{
    __shared__ ull sP[8 * 4 * 16];
    fold_smem((float*)sP, lw, lb, ga, be, 256);

    int lane = threadIdx.x & 31;
    int co   = lane & 15;
    int half = lane >> 4;

    ull Px[4], Py[4], Pz[4], Pc[4];
#pragma unroll
    for (int k = 0; k < 4; k++) {
        int kg = half * 4 + k;
        Px[k] = sP[(kg * 4 + 0) * 16 + co];
        Py[k] = sP[(kg * 4 + 1) * 16 + co];
        Pz[k] = sP[(kg * 4 + 2) * 16 + co];
        Pc[k] = sP[(kg * 4 + 3) * 16 + co];
    }

    int w = (blockIdx.x * 256 + threadIdx.x) >> 5;   // 0..NW16-1

    int eA = w, eB = w + NW16;
    int sA = __ldg(&ei[eA]), dA = __ldg(&ei[NE + eA]);
    int sB = __ldg(&ei[eB]), dB = __ldg(&ei[NE + eB]);
    float4 psA = __ldg(&g_pseudo[eA]);
    float4 psB = __ldg(&g_pseudo[eB]);

    for (int k = 0; k < IT16; k += 2) {
        // x gathers for current pair (only dependent loads in flight)
        const ulonglong2* xrA = (const ulonglong2*)(hin + (size_t)sA * 16) + half * 2;
        const ulonglong2* xrB = (const ulonglong2*)(hin + (size_t)sB * 16) + half * 2;
        ulonglong2 vA0 = __ldg(&xrA[0]), vA1 = __ldg(&xrA[1]);
        ulonglong2 vB0 = __ldg(&xrB[0]), vB1 = __ldg(&xrB[1]);

        int cdA = dA, cdB = dB;
        float4 cpA = psA, cpB = psB;

        // prefetch next pair
        if (k + 2 < IT16) {
            eA += 2 * NW16; eB += 2 * NW16;
            sA = __ldg(&ei[eA]); dA = __ldg(&ei[NE + eA]);
            sB = __ldg(&ei[eB]); dB = __ldg(&ei[NE + eB]);
            psA = __ldg(&g_pseudo[eA]);
            psB = __ldg(&g_pseudo[eB]);
        }

        // edge A
        {
            ull p0 = pack2(cpA.x, cpA.x), p1 = pack2(cpA.y, cpA.y), p2 = pack2(cpA.z, cpA.z);
            ull xv[4] = { vA0.x, vA0.y, vA1.x, vA1.y };
            ull acc = 0;
#pragma unroll
            for (int q = 0; q < 4; q++) {
                ull t = ffma2(p2, Pz[q], Pc[q]);
                t = ffma2(p1, Py[q], t);
                t = ffma2(p0, Px[q], t);
                t = relu2(t);
                acc = ffma2(xv[q], t, acc);
            }
            float lo, hi; unpack2(acc, lo, hi);
            float sum = lo + hi;
            sum += __shfl_xor_sync(0xffffffffu, sum, 16);
            quad_red(sum, co, lane < 16, &aggr[(size_t)cdA * 16 + co]);
        }
        // edge B
        {
            ull p0 = pack2(cpB.x, cpB.x), p1 = pack2(cpB.y, cpB.y), p2 = pack2(cpB.z, cpB.z);
            ull xv[4] = { vB0.x, vB0.y, vB1.x, vB1.y };
            ull acc = 0;
#pragma unroll
            for (int q = 0; q < 4; q++) {
                ull t = ffma2(p2, Pz[q], Pc[q]);
                t = ffma2(p1, Py[q], t);
                t = ffma2(p0, Px[q], t);
                t = relu2(t);
                acc = ffma2(xv[q], t, acc);
            }
            float lo, hi; unpack2(acc, lo, hi);
            float sum = lo + hi;
            sum += __shfl_xor_sync(0xffffffffu, sum, 16);
            quad_red(sum, co, lane < 16, &aggr[(size_t)cdB * 16 + co]);
        }
    }
}

// ---------------------------------------------------------------------------
// Node kernel: 4 threads per node (thread = co-quad). Re-zeroes aggr (+deg on last).
template<int CI, bool ZERODEG>
__global__ void __launch_bounds__(256)
node_kernel(const float* __restrict__ hin,
            const float* __restrict__ root,  // [CI, 16]
            const float* __restrict__ bias,  // [16]
            float* __restrict__ aggr,
            float* __restrict__ hout)        // [NN, 16]
{
    int i = blockIdx.x * blockDim.x + threadIdx.x;
    int n = i >> 2, q = i & 3;
    if (n >= NN) return;

    float inv = 1.0f / fmaxf(g_deg[n], 1.0f);
    if (ZERODEG && q == 0) g_deg[n] = 0.0f;

    float4* ar = (float4*)(aggr + (size_t)n * 16) + q;
    float4 a = *ar;
    float4 bi = __ldg((const float4*)bias + q);
    float acc0 = fmaf(a.x, inv, bi.x);
    float acc1 = fmaf(a.y, inv, bi.y);
    float acc2 = fmaf(a.z, inv, bi.z);
    float acc3 = fmaf(a.w, inv, bi.w);

#pragma unroll
    for (int ci = 0; ci < CI; ci++) {
        float xv = __ldg(&hin[(size_t)n * CI + ci]);
        float4 r = __ldg((const float4*)(root + ci * 16) + q);
        acc0 = fmaf(xv, r.x, acc0);
        acc1 = fmaf(xv, r.y, acc1);
        acc2 = fmaf(xv, r.z, acc2);
        acc3 = fmaf(xv, r.w, acc3);
    }

    float4 o;
    o.x = fmaxf(acc0, 0.0f);
    o.y = fmaxf(acc1, 0.0f);
    o.z = fmaxf(acc2, 0.0f);
    o.w = fmaxf(acc3, 0.0f);
    ((float4*)(hout + (size_t)n * 16))[q] = o;
    *ar = make_float4(0.f, 0.f, 0.f, 0.f);   // reset aggr for next layer / call
}

// ---------------------------------------------------------------------------
__global__ void gather_kernel(const float* __restrict__ h,
                              const float* __restrict__ pos,
                              const int*   __restrict__ batch,
                              const int*   __restrict__ idx,
                              float* __restrict__ out)
{
    int i = blockIdx.x * blockDim.x + threadIdx.x;
    if (i >= NIDX) return;
    int n = idx[i];
    float4* od = (float4*)(out + (size_t)i * 16);
    const float4* hs = (const float4*)(h + (size_t)n * 16);
#pragma unroll
    for (int q = 0; q < 4; q++) od[q] = hs[q];
    out[NIDX * 16 + i * 3 + 0] = pos[n * 3 + 0];
    out[NIDX * 16 + i * 3 + 1] = pos[n * 3 + 1];
    out[NIDX * 16 + i * 3 + 2] = pos[n * 3 + 2];
    reinterpret_cast<int*>(out)[NIDX * 19 + i] = batch[n];
}

// ---------------------------------------------------------------------------
extern "C" void kernel_launch(void* const* d_in, const int* in_sizes, int n_in,
                              void* d_out, int out_size)
{
    const float* x   = (const float*)d_in[0];
    const float* pos = (const float*)d_in[1];
    const float* lw0 = (const float*)d_in[2],  *lb0 = (const float*)d_in[3],
               * g0  = (const float*)d_in[4],  *be0 = (const float*)d_in[5],
               * r0  = (const float*)d_in[6],  *bi0 = (const float*)d_in[7];
    const float* lw1 = (const float*)d_in[8],  *lb1 = (const float*)d_in[9],
               * g1  = (const float*)d_in[10], *be1 = (const float*)d_in[11],
               * r1  = (const float*)d_in[12], *bi1 = (const float*)d_in[13];
    const float* lw2 = (const float*)d_in[14], *lb2 = (const float*)d_in[15],
               * g2  = (const float*)d_in[16], *be2 = (const float*)d_in[17],
               * r2  = (const float*)d_in[18], *bi2 = (const float*)d_in[19];
    const int* batch = (const int*)d_in[20];
    const int* idx   = (const int*)d_in[21];
    const int* ei    = (const int*)d_in[22];
    float* out = (float*)d_out;

    float *aggr, *h1, *h2;
    cudaGetSymbolAddress((void**)&aggr, g_aggr);
    cudaGetSymbolAddress((void**)&h1,   g_h1);
    cudaGetSymbolAddress((void**)&h2,   g_h2);

    dim3 node_grid((NN * 4 + 255) / 256);

    // Layer 0 (CI=8): x -> h1. Also computes pseudo + degree.
    edge8_kernel<<<EB, 256>>>(x, pos, ei, lw0, lb0, g0, be0, aggr);
    node_kernel<8, false><<<node_grid, 256>>>(x, r0, bi0, aggr, h1);

    // Layer 1 (CI=16): h1 -> h2
    edge16_kernel<<<EB, 256>>>(h1, ei, lw1, lb1, g1, be1, aggr);
    node_kernel<16, false><<<node_grid, 256>>>(h1, r1, bi1, aggr, h2);

    // Layer 2 (CI=16): h2 -> h1
    edge16_kernel<<<EB, 256>>>(h2, ei, lw2, lb2, g2, be2, aggr);
    node_kernel<16, true><<<node_grid, 256>>>(h2, r2, bi2, aggr, h1);

    gather_kernel<<<(NIDX + 255) / 256, 256>>>(h1, pos, batch, idx, out);
}

// round 16
// speedup vs baseline: 1.7840x; 1.0130x over previous
#include <cuda_runtime.h>
#include <cuda_bf16.h>

#define NN 50000
#define NE 800000
#define NIDX 25000

typedef unsigned long long ull;

#define EB 2500            // edge-kernel blocks: 640000 threads
#define NSL8 40000         // half-warp slots (edge8): NE/NSL8 = 20 edges/slot exact
#define NW16 20000         // warps (edge16):         NE/NW16 = 40 edges/warp exact
#define IT8  20            // edges per slot (edge8)
#define IT16 40            // edges per warp (edge16)

// Scratch (__device__ globals; zero-initialized at module load).
// Invariants at START of every kernel_launch call:
//   g_deg == 0 (re-zeroed by last node kernel), g_aggr == 0 (re-zeroed by every node kernel).
__device__ float  g_deg [NN];
__device__ float  g_aggr[NN * 16];
__device__ float  g_h1  [NN * 16];
__device__ float  g_h2  [NN * 16];
__device__ float4 g_pseudo[NE];

// ---- packed f32x2 helpers -------------------------------------------------
__device__ __forceinline__ ull ffma2(ull a, ull b, ull c) {
    ull d;
    asm("fma.rn.f32x2 %0, %1, %2, %3;" : "=l"(d) : "l"(a), "l"(b), "l"(c));
    return d;
}
__device__ __forceinline__ ull pack2(float lo, float hi) {
    ull r;
    asm("mov.b64 %0, {%1, %2};" : "=l"(r) : "f"(lo), "f"(hi));
    return r;
}
__device__ __forceinline__ void unpack2(ull v, float& lo, float& hi) {
    asm("mov.b64 {%0, %1}, %2;" : "=f"(lo), "=f"(hi) : "l"(v));
}
__device__ __forceinline__ ull relu2(ull v) {
    float lo, hi;
    unpack2(v, lo, hi);
    lo = fmaxf(lo, 0.0f);
    hi = fmaxf(hi, 0.0f);
    return pack2(lo, hi);
}
__device__ __forceinline__ void red_v4(float* p, float a, float b, float c, float d) {
    asm volatile("red.global.add.v4.f32 [%0], {%1, %2, %3, %4};"
                 :: "l"(p), "f"(a), "f"(b), "f"(c), "f"(d) : "memory");
}

// Collect co-quads and issue one red.v4 per 4 lanes. 'sum' = this lane's co value.
// Lanes with (co&3)==0 && active issue red.v4 covering co..co+3.
__device__ __forceinline__ void quad_red(float sum, int co, bool active, float* addr) {
    float b  = __shfl_xor_sync(0xffffffffu, sum, 1);
    float v0 = (co & 1) ? b : sum;
    float v1 = (co & 1) ? sum : b;
    float c0 = __shfl_xor_sync(0xffffffffu, v0, 2);
    float c1 = __shfl_xor_sync(0xffffffffu, v1, 2);
    if (active && (co & 3) == 0) red_v4(addr, v0, v1, c0, c1);
}

// Fold edge-MLP params into smem (packed over ci-pairs).
// As floats: sf[((k*4+c)*16+co)*2 + (ci&1)], k = ci>>1, c in {Wx,Wy,Wz,const}.
__device__ __forceinline__ void fold_smem(float* sf,
                                          const float* __restrict__ lw,
                                          const float* __restrict__ lb,
                                          const float* __restrict__ ga,
                                          const float* __restrict__ be, int D)
{
    for (int j = threadIdx.x; j < D; j += blockDim.x) {
        float g = ga[j];
        float c0 = lw[j] * g;
        float c1 = lw[D + j] * g;
        float c2 = lw[2 * D + j] * g;
        float c3 = fmaf(lb[j], g, be[j]);
        int ci = j >> 4, co = j & 15;
        int k = ci >> 1, h = ci & 1;
        sf[((k * 4 + 0) * 16 + co) * 2 + h] = c0;
        sf[((k * 4 + 1) * 16 + co) * 2 + h] = c1;
        sf[((k * 4 + 2) * 16 + co) * 2 + h] = c2;
        sf[((k * 4 + 3) * 16 + co) * 2 + h] = c3;
    }
    __syncthreads();
}

// ---------------------------------------------------------------------------
// Layer-0 edge kernel (CI=8): half-warp per edge (lane = co).
// Software-pipelined pairs; also computes pseudo (stored) and degree.
__global__ void __launch_bounds__(256)
edge8_kernel(const float* __restrict__ x,     // [NN, 8]
             const float* __restrict__ pos,   // [NN, 3]
             const int*   __restrict__ ei,    // [2, NE]
             const float* __restrict__ lw, const float* __restrict__ lb,
             const float* __restrict__ ga, const float* __restrict__ be,
             float* __restrict__ aggr)        // [NN, 16]
{
    __shared__ ull sP[4 * 4 * 16];
    fold_smem((float*)sP, lw, lb, ga, be, 128);

    int co = threadIdx.x & 15;
    ull Px[4], Py[4], Pz[4], Pc[4];
#pragma unroll
    for (int k = 0; k < 4; k++) {
        Px[k] = sP[(k * 4 + 0) * 16 + co];
        Py[k] = sP[(k * 4 + 1) * 16 + co];
        Pz[k] = sP[(k * 4 + 2) * 16 + co];
        Pc[k] = sP[(k * 4 + 3) * 16 + co];
    }

    int slot = (blockIdx.x * 256 + threadIdx.x) >> 4;   // 0..NSL8-1

    // prefetch first pair's indices
    int eA = slot, eB = slot + NSL8;
    int sA = __ldg(&ei[eA]), dA = __ldg(&ei[NE + eA]);
    int sB = __ldg(&ei[eB]), dB = __ldg(&ei[NE + eB]);

    for (int k = 0; k < IT8; k += 2) {
        // dependent loads for current pair (issued first)
        float ax = __ldg(&pos[dA * 3 + 0]) - __ldg(&pos[sA * 3 + 0]);
        float ay = __ldg(&pos[dA * 3 + 1]) - __ldg(&pos[sA * 3 + 1]);
        float az = __ldg(&pos[dA * 3 + 2]) - __ldg(&pos[sA * 3 + 2]);
        float bx = __ldg(&pos[dB * 3 + 0]) - __ldg(&pos[sB * 3 + 0]);
        float by = __ldg(&pos[dB * 3 + 1]) - __ldg(&pos[sB * 3 + 1]);
        float bz = __ldg(&pos[dB * 3 + 2]) - __ldg(&pos[sB * 3 + 2]);
        const ulonglong2* xrA = (const ulonglong2*)(x + (size_t)sA * 8);
        const ulonglong2* xrB = (const ulonglong2*)(x + (size_t)sB * 8);
        ulonglong2 vA0 = __ldg(&xrA[0]), vA1 = __ldg(&xrA[1]);
        ulonglong2 vB0 = __ldg(&xrB[0]), vB1 = __ldg(&xrB[1]);

        int cdA = dA, cdB = dB, ceA = eA, ceB = eB;

        // prefetch next pair's indices (independent of compute below)
        if (k + 2 < IT8) {
            eA += 2 * NSL8; eB += 2 * NSL8;
            sA = __ldg(&ei[eA]); dA = __ldg(&ei[NE + eA]);
            sB = __ldg(&ei[eB]); dB = __ldg(&ei[NE + eB]);
        }

        if (co == 0) {
            g_pseudo[ceA] = make_float4(ax, ay, az, 0.f);
            g_pseudo[ceB] = make_float4(bx, by, bz, 0.f);
            atomicAdd(&g_deg[cdA], 1.0f);
            atomicAdd(&g_deg[cdB], 1.0f);
        }

        // edge A
        {
            ull p0 = pack2(ax, ax), p1 = pack2(ay, ay), p2 = pack2(az, az);
            ull xv[4] = { vA0.x, vA0.y, vA1.x, vA1.y };
            ull acc = 0;
#pragma unroll
            for (int q = 0; q < 4; q++) {
                ull w = ffma2(p2, Pz[q], Pc[q]);
                w = ffma2(p1, Py[q], w);
                w = ffma2(p0, Px[q], w);
                w = relu2(w);
                acc = ffma2(xv[q], w, acc);
            }
            float lo, hi; unpack2(acc, lo, hi);
            quad_red(lo + hi, co, true, &aggr[(size_t)cdA * 16 + co]);
        }
        // edge B
        {
            ull p0 = pack2(bx, bx), p1 = pack2(by, by), p2 = pack2(bz, bz);
            ull xv[4] = { vB0.x, vB0.y, vB1.x, vB1.y };
            ull acc = 0;
#pragma unroll
            for (int q = 0; q < 4; q++) {
                ull w = ffma2(p2, Pz[q], Pc[q]);
                w = ffma2(p1, Py[q], w);
                w = ffma2(p0, Px[q], w);
                w = relu2(w);
                acc = ffma2(xv[q], w, acc);
            }
            float lo, hi; unpack2(acc, lo, hi);
            quad_red(lo + hi, co, true, &aggr[(size_t)cdB * 16 + co]);
        }
    }
}

// ---------------------------------------------------------------------------
// CI=16 edge kernel: FULL warp per edge. ci split across half-warps
// (half h handles ci in [8h, 8h+8)), combined via shfl_xor(16). Pipelined pairs.
__global__ void __launch_bounds__(256)
edge16_kernel(const float* __restrict__ hin,  // [NN, 16]
              const int*   __restrict__ ei,   // [2, NE]
              const float* __restrict__ lw, const float* __restrict__ lb,
              const float* __restrict__ ga, const float* __restrict__ be,
              float* __restrict__ aggr)       // [NN, 16]
{
    __shared__ ull sP[8 * 4 * 16];
    fold_smem((float*)sP, lw, lb, ga, be, 256);

    int lane = threadIdx.x & 31;
    int co   = lane & 15;
    int half = lane >> 4;

    ull Px[4], Py[4], Pz[4], Pc[4];
#pragma unroll
    for (int k = 0; k < 4; k++) {
        int kg = half * 4 + k;
        Px[k] = sP[(kg * 4 + 0) * 16 + co];
        Py[k] = sP[(kg * 4 + 1) * 16 + co];
        Pz[k] = sP[(kg * 4 + 2) * 16 + co];
        Pc[k] = sP[(kg * 4 + 3) * 16 + co];
    }

    int w = (blockIdx.x * 256 + threadIdx.x) >> 5;   // 0..NW16-1

    int eA = w, eB = w + NW16;
    int sA = __ldg(&ei[eA]), dA = __ldg(&ei[NE + eA]);
    int sB = __ldg(&ei[eB]), dB = __ldg(&ei[NE + eB]);
    float4 psA = __ldg(&g_pseudo[eA]);
    float4 psB = __ldg(&g_pseudo[eB]);

    for (int k = 0; k < IT16; k += 2) {
        // x gathers for current pair (only dependent loads in flight)
        const ulonglong2* xrA = (const ulonglong2*)(hin + (size_t)sA * 16) + half * 2;
        const ulonglong2* xrB = (const ulonglong2*)(hin + (size_t)sB * 16) + half * 2;
        ulonglong2 vA0 = __ldg(&xrA[0]), vA1 = __ldg(&xrA[1]);
        ulonglong2 vB0 = __ldg(&xrB[0]), vB1 = __ldg(&xrB[1]);

        int cdA = dA, cdB = dB;
        float4 cpA = psA, cpB = psB;

        // prefetch next pair
        if (k + 2 < IT16) {
            eA += 2 * NW16; eB += 2 * NW16;
            sA = __ldg(&ei[eA]); dA = __ldg(&ei[NE + eA]);
            sB = __ldg(&ei[eB]); dB = __ldg(&ei[NE + eB]);
            psA = __ldg(&g_pseudo[eA]);
            psB = __ldg(&g_pseudo[eB]);
        }

        // edge A
        {
            ull p0 = pack2(cpA.x, cpA.x), p1 = pack2(cpA.y, cpA.y), p2 = pack2(cpA.z, cpA.z);
            ull xv[4] = { vA0.x, vA0.y, vA1.x, vA1.y };
            ull acc = 0;
#pragma unroll
            for (int q = 0; q < 4; q++) {
                ull t = ffma2(p2, Pz[q], Pc[q]);
                t = ffma2(p1, Py[q], t);
                t = ffma2(p0, Px[q], t);
                t = relu2(t);
                acc = ffma2(xv[q], t, acc);
            }
            float lo, hi; unpack2(acc, lo, hi);
            float sum = lo + hi;
            sum += __shfl_xor_sync(0xffffffffu, sum, 16);
            quad_red(sum, co, lane < 16, &aggr[(size_t)cdA * 16 + co]);
        }
        // edge B
        {
            ull p0 = pack2(cpB.x, cpB.x), p1 = pack2(cpB.y, cpB.y), p2 = pack2(cpB.z, cpB.z);
            ull xv[4] = { vB0.x, vB0.y, vB1.x, vB1.y };
            ull acc = 0;
#pragma unroll
            for (int q = 0; q < 4; q++) {
                ull t = ffma2(p2, Pz[q], Pc[q]);
                t = ffma2(p1, Py[q], t);
                t = ffma2(p0, Px[q], t);
                t = relu2(t);
                acc = ffma2(xv[q], t, acc);
            }
            float lo, hi; unpack2(acc, lo, hi);
            float sum = lo + hi;
            sum += __shfl_xor_sync(0xffffffffu, sum, 16);
            quad_red(sum, co, lane < 16, &aggr[(size_t)cdB * 16 + co]);
        }
    }
}

// ---------------------------------------------------------------------------
// Node kernel: 4 threads per node (thread = co-quad). Re-zeroes aggr (+deg on last).
// hin row read as wide vectors (4x LDG.128 for CI=16, 2x for CI=8) instead of
// CI scalar LDG.32s.
template<int CI, bool ZERODEG>
__global__ void __launch_bounds__(256)
node_kernel(const float* __restrict__ hin,
            const float* __restrict__ root,  // [CI, 16]
            const float* __restrict__ bias,  // [16]
            float* __restrict__ aggr,
            float* __restrict__ hout)        // [NN, 16]
{
    int i = blockIdx.x * blockDim.x + threadIdx.x;
    int n = i >> 2, q = i & 3;
    if (n >= NN) return;

    float inv = 1.0f / fmaxf(g_deg[n], 1.0f);
    if (ZERODEG && q == 0) g_deg[n] = 0.0f;

    // Wide-load the hin row (contiguous CI floats) into registers.
    float hv[CI];
    const float4* hrow = (const float4*)(hin + (size_t)n * CI);
#pragma unroll
    for (int v = 0; v < CI / 4; v++) {
        float4 hq = __ldg(&hrow[v]);
        hv[4 * v + 0] = hq.x;
        hv[4 * v + 1] = hq.y;
        hv[4 * v + 2] = hq.z;
        hv[4 * v + 3] = hq.w;
    }

    float4* ar = (float4*)(aggr + (size_t)n * 16) + q;
    float4 a = *ar;
    float4 bi = __ldg((const float4*)bias + q);
    float acc0 = fmaf(a.x, inv, bi.x);
    float acc1 = fmaf(a.y, inv, bi.y);
    float acc2 = fmaf(a.z, inv, bi.z);
    float acc3 = fmaf(a.w, inv, bi.w);

#pragma unroll
    for (int ci = 0; ci < CI; ci++) {
        float4 r = __ldg((const float4*)(root + ci * 16) + q);
        acc0 = fmaf(hv[ci], r.x, acc0);
        acc1 = fmaf(hv[ci], r.y, acc1);
        acc2 = fmaf(hv[ci], r.z, acc2);
        acc3 = fmaf(hv[ci], r.w, acc3);
    }

    float4 o;
    o.x = fmaxf(acc0, 0.0f);
    o.y = fmaxf(acc1, 0.0f);
    o.z = fmaxf(acc2, 0.0f);
    o.w = fmaxf(acc3, 0.0f);
    ((float4*)(hout + (size_t)n * 16))[q] = o;
    *ar = make_float4(0.f, 0.f, 0.f, 0.f);   // reset aggr for next layer / call
}

// ---------------------------------------------------------------------------
__global__ void gather_kernel(const float* __restrict__ h,
                              const float* __restrict__ pos,
                              const int*   __restrict__ batch,
                              const int*   __restrict__ idx,
                              float* __restrict__ out)
{
    int i = blockIdx.x * blockDim.x + threadIdx.x;
    if (i >= NIDX) return;
    int n = idx[i];
    float4* od = (float4*)(out + (size_t)i * 16);
    const float4* hs = (const float4*)(h + (size_t)n * 16);
#pragma unroll
    for (int q = 0; q < 4; q++) od[q] = hs[q];
    out[NIDX * 16 + i * 3 + 0] = pos[n * 3 + 0];
    out[NIDX * 16 + i * 3 + 1] = pos[n * 3 + 1];
    out[NIDX * 16 + i * 3 + 2] = pos[n * 3 + 2];
    reinterpret_cast<int*>(out)[NIDX * 19 + i] = batch[n];
}

// ---------------------------------------------------------------------------
extern "C" void kernel_launch(void* const* d_in, const int* in_sizes, int n_in,
                              void* d_out, int out_size)
{
    const float* x   = (const float*)d_in[0];
    const float* pos = (const float*)d_in[1];
    const float* lw0 = (const float*)d_in[2],  *lb0 = (const float*)d_in[3],
               * g0  = (const float*)d_in[4],  *be0 = (const float*)d_in[5],
               * r0  = (const float*)d_in[6],  *bi0 = (const float*)d_in[7];
    const float* lw1 = (const float*)d_in[8],  *lb1 = (const float*)d_in[9],
               * g1  = (const float*)d_in[10], *be1 = (const float*)d_in[11],
               * r1  = (const float*)d_in[12], *bi1 = (const float*)d_in[13];
    const float* lw2 = (const float*)d_in[14], *lb2 = (const float*)d_in[15],
               * g2  = (const float*)d_in[16], *be2 = (const float*)d_in[17],
               * r2  = (const float*)d_in[18], *bi2 = (const float*)d_in[19];
    const int* batch = (const int*)d_in[20];
    const int* idx   = (const int*)d_in[21];
    const int* ei    = (const int*)d_in[22];
    float* out = (float*)d_out;

    float *aggr, *h1, *h2;
    cudaGetSymbolAddress((void**)&aggr, g_aggr);
    cudaGetSymbolAddress((void**)&h1,   g_h1);
    cudaGetSymbolAddress((void**)&h2,   g_h2);

    dim3 node_grid((NN * 4 + 255) / 256);

    // Layer 0 (CI=8): x -> h1. Also computes pseudo + degree.
    edge8_kernel<<<EB, 256>>>(x, pos, ei, lw0, lb0, g0, be0, aggr);
    node_kernel<8, false><<<node_grid, 256>>>(x, r0, bi0, aggr, h1);

    // Layer 1 (CI=16): h1 -> h2
    edge16_kernel<<<EB, 256>>>(h1, ei, lw1, lb1, g1, be1, aggr);
    node_kernel<16, false><<<node_grid, 256>>>(h1, r1, bi1, aggr, h2);

    // Layer 2 (CI=16): h2 -> h1
    edge16_kernel<<<EB, 256>>>(h2, ei, lw2, lb2, g2, be2, aggr);
    node_kernel<16, true><<<node_grid, 256>>>(h2, r2, bi2, aggr, h1);

    gather_kernel<<<(NIDX + 255) / 256, 256>>>(h1, pos, batch, idx, out);
}